// round 17
// baseline (speedup 1.0000x reference)
#include <cuda_runtime.h>
#include <cuda_bf16.h>
#include <cuda_fp16.h>
#include <mma.h>
#include <math.h>

using namespace nvcuda;

// ---------------------------------------------------------------------------
// GAT 3-layer forward on GB300.
//   Pre-convert features + weights to fp16 (tiny kernels, overlapped).
//   feat = H_in @ W via HMMA (wmma, BK=32, reg double-buffer, pure fp16 staging)
//   agg4: warp-per-(node, 128-col half), smem weights, late normalize.
//   CSR build + weight converts overlapped on a second stream.
// ---------------------------------------------------------------------------

#define MAXN 50000
#define MAXE 800000
#define SMAXD 96

__device__ __half g_feat[MAXN * 256];
__device__ __half g_bufA[MAXN * 256];
__device__ __half g_bufB[MAXN * 256];
__device__ __half g_featH[MAXN * 128];
__device__ __half g_w1h[128 * 256];
__device__ __half g_w2h[256 * 256];
__device__ __half g_w3h[256 * 64];
__device__ float  g_el[MAXN * 4];
__device__ float  g_er[MAXN * 4];
__device__ float  g_ew[MAXE * 4];
__device__ int    g_rowptr[MAXN + 1];
__device__ int    g_cursor[MAXN];
__device__ int    g_cnt[MAXN];
__device__ int    g_colsrc[MAXE];

// ---------------------------------------------------------------------------
// fp32 -> fp16 conversion (vectorized)
// ---------------------------------------------------------------------------
__global__ void cvt_f2h_kernel(const float* __restrict__ in, __half* __restrict__ out, int n) {
    int i = (blockIdx.x * blockDim.x + threadIdx.x) * 4;
    if (i < n) {
        float4 f = *(const float4*)&in[i];
        union { __half2 h2[2]; uint2 u; } p;
        p.h2[0] = __floats2half2_rn(f.x, f.y);
        p.h2[1] = __floats2half2_rn(f.z, f.w);
        *(uint2*)&out[i] = p.u;
    }
}

// ---------------------------------------------------------------------------
// CSR build
// ---------------------------------------------------------------------------
__global__ void hist_kernel(const int* __restrict__ dst, int* __restrict__ cnt, int E) {
    int i = blockIdx.x * blockDim.x + threadIdx.x;
    if (i < E) atomicAdd(&cnt[dst[i]], 1);
}

__global__ void scan_kernel(const int* __restrict__ cnt, int* __restrict__ rowptr,
                            int* __restrict__ cursor, int N, int E) {
    __shared__ int sums[1024];
    int tid = threadIdx.x;
    int chunk = (N + 1023) >> 10;
    int start = tid * chunk;
    int end = min(start + chunk, N);
    int s = 0;
    for (int i = start; i < end; i++) s += cnt[i];
    sums[tid] = s;
    __syncthreads();
    for (int off = 1; off < 1024; off <<= 1) {
        int v = (tid >= off) ? sums[tid - off] : 0;
        __syncthreads();
        sums[tid] += v;
        __syncthreads();
    }
    int run = sums[tid] - s;
    for (int i = start; i < end; i++) {
        rowptr[i] = run;
        cursor[i] = run;
        run += cnt[i];
    }
    if (tid == 0) rowptr[N] = E;
}

__global__ void scatter_kernel(const int* __restrict__ src, const int* __restrict__ dst,
                               int* __restrict__ cursor, int* __restrict__ colsrc, int E) {
    int i = blockIdx.x * blockDim.x + threadIdx.x;
    if (i < E) {
        int p = atomicAdd(&cursor[dst[i]], 1);
        colsrc[p] = src[i];
    }
}

// ---------------------------------------------------------------------------
// HMMA GEMM 128x64 block, BK=32, 8 warps (4x2), warp tile 32x32.
// All-fp16 inputs; register double-buffered staging. C fp16.
// Fused fp32 el/er epilogue (block column == one head).
// ---------------------------------------------------------------------------
__global__ __launch_bounds__(256) void hgemm_fused_kernel(
    const __half* __restrict__ A, const __half* __restrict__ B, __half* __restrict__ C,
    const float* __restrict__ al, const float* __restrict__ arv,
    float* __restrict__ el, float* __restrict__ er,
    int M, int K, int Nc, int H) {
    constexpr int LDA = 40;
    constexpr int LDB = 72;
    constexpr int LDC = 72;
    __shared__ __align__(16) float smemF[128 * LDC];
    __half* As = reinterpret_cast<__half*>(smemF);
    __half* Bs = As + 2 * 128 * LDA;
    float*  Cs = smemF;

    const int t = threadIdx.x;
    const int m0 = blockIdx.y * 128;
    const int n0 = blockIdx.x * 64;
    const int head = blockIdx.x;
    const int wid = t >> 5;
    const int wm = wid >> 1;
    const int wn = wid & 1;

    wmma::fragment<wmma::accumulator, 16, 16, 16, float> acc[2][2];
    #pragma unroll
    for (int i = 0; i < 2; i++)
        #pragma unroll
        for (int j = 0; j < 2; j++) wmma::fill_fragment(acc[i][j], 0.f);

    const int arow = t >> 1;
    const int acol = (t & 1) * 16;
    const int brow = t >> 3;
    const int bcol = (t & 7) * 8;
    const bool aval = (m0 + arow) < M;

    auto loadA = [&](int k0, uint4& u0, uint4& u1) {
        if (aval) {
            const __half* ap = A + (size_t)(m0 + arow) * K + k0 + acol;
            u0 = *(const uint4*)(ap + 0);
            u1 = *(const uint4*)(ap + 8);
        } else {
            u0 = make_uint4(0, 0, 0, 0);
            u1 = make_uint4(0, 0, 0, 0);
        }
    };
    auto loadB = [&](int k0, uint4& u) {
        u = *(const uint4*)(B + (size_t)(k0 + brow) * Nc + n0 + bcol);
    };
    auto storeStage = [&](int b, uint4 a0, uint4 a1, uint4 bu) {
        __half* abase = As + b * 128 * LDA + arow * LDA + acol;
        *(uint4*)(abase + 0) = a0;
        *(uint4*)(abase + 8) = a1;
        *(uint4*)(Bs + b * 32 * LDB + brow * LDB + bcol) = bu;
    };
    auto mmaStage = [&](int b) {
        #pragma unroll
        for (int kk = 0; kk < 32; kk += 16) {
            wmma::fragment<wmma::matrix_a, 16, 16, 16, __half, wmma::row_major> af[2];
            wmma::fragment<wmma::matrix_b, 16, 16, 16, __half, wmma::row_major> bf[2];
            #pragma unroll
            for (int i = 0; i < 2; i++)
                wmma::load_matrix_sync(af[i],
                    As + b * 128 * LDA + (wm * 32 + i * 16) * LDA + kk, LDA);
            #pragma unroll
            for (int j = 0; j < 2; j++)
                wmma::load_matrix_sync(bf[j],
                    Bs + b * 32 * LDB + kk * LDB + wn * 32 + j * 16, LDB);
            #pragma unroll
            for (int i = 0; i < 2; i++)
                #pragma unroll
                for (int j = 0; j < 2; j++)
                    wmma::mma_sync(acc[i][j], af[i], bf[j], acc[i][j]);
        }
    };

    {
        uint4 a0, a1, bu;
        loadA(0, a0, a1);
        loadB(0, bu);
        storeStage(0, a0, a1, bu);
    }
    __syncthreads();

    int buf = 0;
    for (int k0 = 32; k0 < K; k0 += 32) {
        uint4 a0, a1, bu;
        loadA(k0, a0, a1);
        loadB(k0, bu);
        mmaStage(buf);
        int nb = buf ^ 1;
        storeStage(nb, a0, a1, bu);
        __syncthreads();
        buf = nb;
    }
    mmaStage(buf);
    __syncthreads();

    #pragma unroll
    for (int i = 0; i < 2; i++)
        #pragma unroll
        for (int j = 0; j < 2; j++)
            wmma::store_matrix_sync(Cs + (wm * 32 + i * 16) * LDC + wn * 32 + j * 16,
                                    acc[i][j], LDC, wmma::mem_row_major);
    __syncthreads();

    const int row = t >> 1;
    const int pair = t & 1;
    const int cbase = pair * 32;
    float l = 0.f, r = 0.f;
    __half2 hp[16];
    #pragma unroll
    for (int j = 0; j < 32; j += 2) {
        float c0v = Cs[row * LDC + cbase + j];
        float c1v = Cs[row * LDC + cbase + j + 1];
        hp[j >> 1] = __floats2half2_rn(c0v, c1v);
        l += c0v * al[head * 64 + cbase + j] + c1v * al[head * 64 + cbase + j + 1];
        r += c0v * arv[head * 64 + cbase + j] + c1v * arv[head * 64 + cbase + j + 1];
    }
    l += __shfl_xor_sync(0xffffffffu, l, 1);
    r += __shfl_xor_sync(0xffffffffu, r, 1);
    if (m0 + row < M) {
        uint4* dst = (uint4*)&C[(size_t)(m0 + row) * Nc + n0 + cbase];
        uint4* srcp = (uint4*)hp;
        dst[0] = srcp[0]; dst[1] = srcp[1]; dst[2] = srcp[2]; dst[3] = srcp[3];
        if (pair == 0) {
            el[(size_t)(m0 + row) * H + head] = l;
            er[(size_t)(m0 + row) * H + head] = r;
        }
    }
}

__device__ __forceinline__ float lrelu(float x) { return x > 0.f ? x : 0.2f * x; }

// ---------------------------------------------------------------------------
// Aggregation H=4, D=64: one warp per (node, 128-col half).
// Lane owns 4 cols (c = half*128 + lane*4); head = half*2 + (lane>>4).
// Pass A computes only this half's 2 heads (float2 el gather).
// ---------------------------------------------------------------------------
__global__ __launch_bounds__(256) void agg4_kernel(
    const __half* __restrict__ feat, const float* __restrict__ el,
    const float* __restrict__ er, const float* __restrict__ bias,
    const int* __restrict__ rowptr, const int* __restrict__ colsrc,
    float* __restrict__ ew, __half* __restrict__ out, int N) {
    __shared__ int   s_src[8][SMAXD];
    __shared__ float s_w[8][SMAXD * 2];
    const unsigned FULL = 0xffffffffu;
    const int wid = threadIdx.x >> 5;
    const int lane = threadIdx.x & 31;
    int gw = (blockIdx.x * blockDim.x + threadIdx.x) >> 5;
    if (gw >= 2 * N) return;
    const int n = gw >> 1;
    const int half = gw & 1;
    const int base = rowptr[n];
    const int deg = rowptr[n + 1] - base;
    const bool lo = (lane < 16);
    const bool fast = (deg <= SMAXD);

    float2 r2 = *(const float2*)&er[(size_t)n * 4 + half * 2];
    float s0 = 0.f, s1 = 0.f;

    // Pass A: this half's 2 head-weights per edge
    for (int i0 = 0; i0 < deg; i0 += 32) {
        int i = i0 + lane;
        bool act = i < deg;
        int s = colsrc[base + (act ? i : 0)];
        float2 l2 = *(const float2*)&el[(size_t)s * 4 + half * 2];
        float w0 = __expf(lrelu(l2.x + r2.x));
        float w1 = __expf(lrelu(l2.y + r2.y));
        if (act) {
            if (fast) {
                s_src[wid][i] = s;
                *(float2*)&s_w[wid][i * 2] = make_float2(w0, w1);
            } else {
                *(float2*)&ew[(size_t)(base + i) * 4 + half * 2] = make_float2(w0, w1);
            }
            s0 += w0; s1 += w1;
        }
    }
    __syncwarp();

    // Paired reduction: lanes<16 end with head(half*2), lanes>=16 head(half*2+1)
    float tA = lo ? s0 : s1;
    float oA = lo ? s1 : s0;
    tA += __shfl_xor_sync(FULL, oA, 16);
    #pragma unroll
    for (int o = 8; o; o >>= 1) tA += __shfl_xor_sync(FULL, tA, o);
    const float is = (deg > 0) ? 1.f / tA : 0.f;   // matches lane's head (lane>>4)
    const int hsel = lane >> 4;                     // head-within-half
    const int c = half * 128 + lane * 4;

    // Pass B: 1 x LDG.64 (4 halfs) per lane per edge, unroll 8
    float a[4] = {0.f, 0.f, 0.f, 0.f};
    if (fast) {
        int i = 0;
        for (; i + 8 <= deg; i += 8) {
            uint2 q[8];
            float wv[8];
            #pragma unroll
            for (int u = 0; u < 8; u++) {
                int s = s_src[wid][i + u];
                wv[u] = s_w[wid][(i + u) * 2 + hsel];
                q[u] = *(const uint2*)&feat[(size_t)s * 256 + c];
            }
            #pragma unroll
            for (int u = 0; u < 8; u++) {
                __half2* hh = (__half2*)&q[u];
                float2 f0 = __half22float2(hh[0]);
                float2 f1 = __half22float2(hh[1]);
                a[0] += f0.x * wv[u]; a[1] += f0.y * wv[u];
                a[2] += f1.x * wv[u]; a[3] += f1.y * wv[u];
            }
        }
        for (; i < deg; i++) {
            int s = s_src[wid][i];
            float w = s_w[wid][i * 2 + hsel];
            uint2 q = *(const uint2*)&feat[(size_t)s * 256 + c];
            __half2* hh = (__half2*)&q;
            float2 f0 = __half22float2(hh[0]);
            float2 f1 = __half22float2(hh[1]);
            a[0] += f0.x * w; a[1] += f0.y * w;
            a[2] += f1.x * w; a[3] += f1.y * w;
        }
    } else {
        for (int i = 0; i < deg; i++) {
            int s = colsrc[base + i];
            float w = ew[(size_t)(base + i) * 4 + half * 2 + hsel];
            uint2 q = *(const uint2*)&feat[(size_t)s * 256 + c];
            __half2* hh = (__half2*)&q;
            float2 f0 = __half22float2(hh[0]);
            float2 f1 = __half22float2(hh[1]);
            a[0] += f0.x * w; a[1] += f0.y * w;
            a[2] += f1.x * w; a[3] += f1.y * w;
        }
    }
    float4 b4 = *(const float4*)&bias[c];
    a[0] = fmaxf(a[0] * is + b4.x, 0.f);
    a[1] = fmaxf(a[1] * is + b4.y, 0.f);
    a[2] = fmaxf(a[2] * is + b4.z, 0.f);
    a[3] = fmaxf(a[3] * is + b4.w, 0.f);
    union { __half2 h2[2]; uint2 u; } p;
    p.h2[0] = __floats2half2_rn(a[0], a[1]);
    p.h2[1] = __floats2half2_rn(a[2], a[3]);
    *(uint2*)&out[(size_t)n * 256 + c] = p.u;
}

// ---------------------------------------------------------------------------
// Aggregation H=1, D=64: one warp per dst node, fp16 gather, fp32 output.
// ---------------------------------------------------------------------------
__global__ __launch_bounds__(256) void agg1_kernel(
    const __half* __restrict__ feat, const float* __restrict__ el,
    const float* __restrict__ er, const float* __restrict__ bias,
    const int* __restrict__ rowptr, const int* __restrict__ colsrc,
    float* __restrict__ ew, float* __restrict__ out, int N) {
    __shared__ int   s_src[8][SMAXD];
    __shared__ float s_w[8][SMAXD];
    const unsigned FULL = 0xffffffffu;
    const int wid = threadIdx.x >> 5;
    const int lane = threadIdx.x & 31;
    int n = (blockIdx.x * blockDim.x + threadIdx.x) >> 5;
    if (n >= N) return;
    const int base = rowptr[n];
    const int deg = rowptr[n + 1] - base;
    const float rn = er[n];
    const bool fast = (deg <= SMAXD);

    float s0 = 0.f;
    for (int i0 = 0; i0 < deg; i0 += 32) {
        int i = i0 + lane;
        bool act = i < deg;
        int s = colsrc[base + (act ? i : 0)];
        float w = __expf(lrelu(el[s] + rn));
        if (act) {
            if (fast) { s_src[wid][i] = s; s_w[wid][i] = w; }
            else      { ew[base + i] = w; }
            s0 += w;
        }
    }
    __syncwarp();
    #pragma unroll
    for (int o = 16; o; o >>= 1) s0 += __shfl_xor_sync(FULL, s0, o);
    const float is = (deg > 0) ? 1.f / s0 : 0.f;
    const int c = lane * 2;

    float2 a = make_float2(0.f, 0.f);
    if (fast) {
        int i = 0;
        for (; i + 8 <= deg; i += 8) {
            int   sI[8];
            float wv[8];
            #pragma unroll
            for (int u = 0; u < 8; u++) {
                sI[u] = s_src[wid][i + u];
                wv[u] = s_w[wid][i + u];
            }
            #pragma unroll
            for (int u = 0; u < 8; u++) {
                __half2 hv = *(const __half2*)&feat[(size_t)sI[u] * 64 + c];
                float2 f = __half22float2(hv);
                a.x += f.x * wv[u];
                a.y += f.y * wv[u];
            }
        }
        for (; i < deg; i++) {
            float w = s_w[wid][i];
            __half2 hv = *(const __half2*)&feat[(size_t)s_src[wid][i] * 64 + c];
            float2 f = __half22float2(hv);
            a.x += f.x * w;
            a.y += f.y * w;
        }
    } else {
        for (int i = 0; i < deg; i++) {
            int s = colsrc[base + i];
            float w = ew[base + i];
            __half2 hv = *(const __half2*)&feat[(size_t)s * 64 + c];
            float2 f = __half22float2(hv);
            a.x += f.x * w;
            a.y += f.y * w;
        }
    }
    a.x = a.x * is + bias[c];
    a.y = a.y * is + bias[c + 1];
    *(float2*)&out[(size_t)n * 64 + c] = a;
}

// ---------------------------------------------------------------------------
// kernel_launch
// ---------------------------------------------------------------------------
extern "C" void kernel_launch(void* const* d_in, const int* in_sizes, int n_in,
                              void* d_out, int out_size) {
    const float* features = (const float*)d_in[0];
    const int*   src      = (const int*)d_in[1];
    const int*   dst      = (const int*)d_in[2];
    const float* W1  = (const float*)d_in[3];
    const float* al1 = (const float*)d_in[4];
    const float* ar1 = (const float*)d_in[5];
    const float* b1  = (const float*)d_in[6];
    const float* W2  = (const float*)d_in[7];
    const float* al2 = (const float*)d_in[8];
    const float* ar2 = (const float*)d_in[9];
    const float* b2  = (const float*)d_in[10];
    const float* W3  = (const float*)d_in[11];
    const float* al3 = (const float*)d_in[12];
    const float* ar3 = (const float*)d_in[13];
    const float* b3  = (const float*)d_in[14];

    const int N = in_sizes[0] / 128;
    const int E = in_sizes[1];

    __half *feat, *bufA, *bufB, *featH, *w1h, *w2h, *w3h;
    float *el, *er, *ew;
    int *rowptr, *cursor, *cnt, *colsrc;
    cudaGetSymbolAddress((void**)&feat,   g_feat);
    cudaGetSymbolAddress((void**)&bufA,   g_bufA);
    cudaGetSymbolAddress((void**)&bufB,   g_bufB);
    cudaGetSymbolAddress((void**)&featH,  g_featH);
    cudaGetSymbolAddress((void**)&w1h,    g_w1h);
    cudaGetSymbolAddress((void**)&w2h,    g_w2h);
    cudaGetSymbolAddress((void**)&w3h,    g_w3h);
    cudaGetSymbolAddress((void**)&el,     g_el);
    cudaGetSymbolAddress((void**)&er,     g_er);
    cudaGetSymbolAddress((void**)&ew,     g_ew);
    cudaGetSymbolAddress((void**)&rowptr, g_rowptr);
    cudaGetSymbolAddress((void**)&cursor, g_cursor);
    cudaGetSymbolAddress((void**)&cnt,    g_cnt);
    cudaGetSymbolAddress((void**)&colsrc, g_colsrc);

    static cudaStream_t s_aux = nullptr;
    static cudaEvent_t e_fork = nullptr, e_join = nullptr;
    if (s_aux == nullptr) {
        cudaStreamCreateWithFlags(&s_aux, cudaStreamNonBlocking);
        cudaEventCreateWithFlags(&e_fork, cudaEventDisableTiming);
        cudaEventCreateWithFlags(&e_join, cudaEventDisableTiming);
    }

    // --- aux stream: weight converts (layers 2-3) + CSR build ---
    cudaEventRecord(e_fork, 0);
    cudaStreamWaitEvent(s_aux, e_fork, 0);
    cvt_f2h_kernel<<<(256 * 256 / 4 + 255) / 256, 256, 0, s_aux>>>(W2, w2h, 256 * 256);
    cvt_f2h_kernel<<<(256 * 64 / 4 + 255) / 256, 256, 0, s_aux>>>(W3, w3h, 256 * 64);
    cudaMemsetAsync(cnt, 0, (size_t)N * sizeof(int), s_aux);
    hist_kernel<<<(E + 255) / 256, 256, 0, s_aux>>>(dst, cnt, E);
    scan_kernel<<<1, 1024, 0, s_aux>>>(cnt, rowptr, cursor, N, E);
    scatter_kernel<<<(E + 255) / 256, 256, 0, s_aux>>>(src, dst, cursor, colsrc, E);
    cudaEventRecord(e_join, s_aux);

    // --- default stream: feature + W1 converts (needed by GEMM1) ---
    cvt_f2h_kernel<<<((N * 128) / 4 + 255) / 256, 256>>>(features, featH, N * 128);
    cvt_f2h_kernel<<<(128 * 256 / 4 + 255) / 256, 256>>>(W1, w1h, 128 * 256);

    const int aggGrid4 = (2 * N + 7) / 8;
    const int aggGrid1 = (N + 7) / 8;
    const int mblocks = (N + 127) / 128;

    // --- Layer 1: IN=128 -> 256 ---
    {
        dim3 grid(4, mblocks);
        hgemm_fused_kernel<<<grid, 256>>>(featH, w1h, feat, al1, ar1, el, er,
                                          N, 128, 256, 4);
        cudaStreamWaitEvent(0, e_join, 0);
        agg4_kernel<<<aggGrid4, 256>>>(feat, el, er, b1, rowptr, colsrc, ew, bufA, N);
    }
    // --- Layer 2: 256 -> 256 ---
    {
        dim3 grid(4, mblocks);
        hgemm_fused_kernel<<<grid, 256>>>(bufA, w2h, feat, al2, ar2, el, er,
                                          N, 256, 256, 4);
        agg4_kernel<<<aggGrid4, 256>>>(feat, el, er, b2, rowptr, colsrc, ew, bufB, N);
    }
    // --- Layer 3: 256 -> 64 (H=1) ---
    {
        dim3 grid(1, mblocks);
        hgemm_fused_kernel<<<grid, 256>>>(bufB, w3h, feat, al3, ar3, el, er,
                                          N, 256, 64, 1);
        agg1_kernel<<<aggGrid1, 256>>>(feat, el, er, b3, rowptr, colsrc, ew, (float*)d_out, N);
    }
}